// round 6
// baseline (speedup 1.0000x reference)
#include <cuda_runtime.h>
#include <cuda_fp16.h>
#include <cstdint>

#define NN 4096
#define FF 256

// ---------------- scratch (device globals; no allocations) ----------------
__device__ float g_h[NN * FF];                    // 4 MB fp32 h
__device__ float g_e1[NN];
__device__ float g_e2[NN];
__device__ float g_tw[NN];                        // e1[r] * t[r]
__device__ float g_wnode[NN];
__device__ unsigned int g_hmax_bits;              // max |h| (float bits, >=0)
__device__ float g_S;                             // fp16 scale
__device__ float g_invS;
__device__ __half g_adjh[(size_t)NN * NN];        // 32 MB  adj as fp16 [4096][4096]
__device__ __half g_gh[(size_t)NN * FF];          // 2 MB   S * wnode_j * h[j][n], fp16
__device__ float g_part[4 * (size_t)NN * FF];     // 16 MB  split-K partials

// ---------------- kernel 1: h = x @ W^T + b (fp32 SIMT tiled) ----------------
__global__ __launch_bounds__(256) void gemm_h_kernel(const float* __restrict__ x,
                                                     const float* __restrict__ W,
                                                     const float* __restrict__ b) {
    __shared__ __align__(16) float xs[16][68];
    __shared__ __align__(16) float ws[16][68];
    const int t = threadIdx.x;
    const int tx = t & 15, ty = t >> 4;
    const int bm = blockIdx.x, bn = blockIdx.y;
    const int r = t >> 2, seg = t & 3;

    float acc[4][4];
#pragma unroll
    for (int i = 0; i < 4; i++)
#pragma unroll
        for (int j = 0; j < 4; j++) acc[i][j] = 0.f;

    for (int kt = 0; kt < 16; ++kt) {
        float4 xv = *(const float4*)(x + (size_t)(bm * 64 + r) * 256 + kt * 16 + seg * 4);
        float4 wv = *(const float4*)(W + (size_t)(bn * 64 + r) * 256 + kt * 16 + seg * 4);
        xs[seg * 4 + 0][r] = xv.x; xs[seg * 4 + 1][r] = xv.y;
        xs[seg * 4 + 2][r] = xv.z; xs[seg * 4 + 3][r] = xv.w;
        ws[seg * 4 + 0][r] = wv.x; ws[seg * 4 + 1][r] = wv.y;
        ws[seg * 4 + 2][r] = wv.z; ws[seg * 4 + 3][r] = wv.w;
        __syncthreads();
#pragma unroll
        for (int k = 0; k < 16; ++k) {
            float4 xa = *(const float4*)&xs[k][ty * 4];
            float4 wb = *(const float4*)&ws[k][tx * 4];
            float xr[4] = {xa.x, xa.y, xa.z, xa.w};
            float wr[4] = {wb.x, wb.y, wb.z, wb.w};
#pragma unroll
            for (int i = 0; i < 4; i++)
#pragma unroll
                for (int j = 0; j < 4; j++) acc[i][j] += xr[i] * wr[j];
        }
        __syncthreads();
    }
#pragma unroll
    for (int i = 0; i < 4; i++) {
        int row = bm * 64 + ty * 4 + i;
#pragma unroll
        for (int j = 0; j < 4; j++) {
            int col = bn * 64 + tx * 4 + j;
            g_h[(size_t)row * 256 + col] = acc[i][j] + b[col];
        }
    }
}

// ---------------- kernel 2: e1/e2 = exp(h.w1/2); also global max|h| ----------------
__global__ __launch_bounds__(256) void a12_kernel(const float* __restrict__ att_w) {
    __shared__ float aw[512];
    const int t = threadIdx.x;
    aw[t] = att_w[t];
    aw[t + 256] = att_w[t + 256];
    __syncthreads();
    const int warp = t >> 5, lane = t & 31;
    const int row = blockIdx.x * 8 + warp;
    const float* hr = g_h + (size_t)row * 256;
    float s1 = 0.f, s2 = 0.f, hm = 0.f;
#pragma unroll
    for (int q = 0; q < 2; q++) {
        int f = lane * 8 + q * 4;
        float4 hv = *(const float4*)(hr + f);
        float4 w1 = *(const float4*)(aw + f);
        float4 w2 = *(const float4*)(aw + 256 + f);
        s1 += hv.x * w1.x + hv.y * w1.y + hv.z * w1.z + hv.w * w1.w;
        s2 += hv.x * w2.x + hv.y * w2.y + hv.z * w2.z + hv.w * w2.w;
        hm = fmaxf(hm, fmaxf(fmaxf(fabsf(hv.x), fabsf(hv.y)),
                             fmaxf(fabsf(hv.z), fabsf(hv.w))));
    }
#pragma unroll
    for (int d = 16; d; d >>= 1) {
        s1 += __shfl_down_sync(0xffffffffu, s1, d);
        s2 += __shfl_down_sync(0xffffffffu, s2, d);
        hm = fmaxf(hm, __shfl_down_sync(0xffffffffu, hm, d));
    }
    if (lane == 0) {
        g_e1[row] = expf(s1);
        g_e2[row] = expf(s2);
        atomicMax(&g_hmax_bits, __float_as_uint(hm));  // |h|>=0: uint order == float order
    }
}

// ---------------- kernel 3: t[i] = sum_j adj[i,j]*e2[j]; adj -> fp16; tw = e1*t ----------------
__global__ __launch_bounds__(256) void row_stats_kernel(const int* __restrict__ adj) {
    const int r = blockIdx.x, t = threadIdx.x;
    const int4* arow = (const int4*)(adj + (size_t)r * 4096) + t * 4;
    float s = 0.f;
    __align__(16) __half ob[16];
#pragma unroll
    for (int q = 0; q < 4; q++) {
        int4 a = arow[q];
        int j = t * 16 + q * 4;
        float4 ev = *(const float4*)(g_e2 + j);
        int f0 = (a.x == 1), f1 = (a.y == 1), f2 = (a.z == 1), f3 = (a.w == 1);
        s += (f0 ? ev.x : 0.f) + (f1 ? ev.y : 0.f) + (f2 ? ev.z : 0.f) + (f3 ? ev.w : 0.f);
        ob[q * 4 + 0] = __ushort_as_half(f0 ? (unsigned short)0x3C00 : (unsigned short)0);
        ob[q * 4 + 1] = __ushort_as_half(f1 ? (unsigned short)0x3C00 : (unsigned short)0);
        ob[q * 4 + 2] = __ushort_as_half(f2 ? (unsigned short)0x3C00 : (unsigned short)0);
        ob[q * 4 + 3] = __ushort_as_half(f3 ? (unsigned short)0x3C00 : (unsigned short)0);
    }
    int4* dst = (int4*)(g_adjh + (size_t)r * 4096 + t * 16);
    dst[0] = ((int4*)ob)[0];
    dst[1] = ((int4*)ob)[1];
    const int lane = t & 31, warp = t >> 5;
#pragma unroll
    for (int d = 16; d; d >>= 1) s += __shfl_down_sync(0xffffffffu, s, d);
    __shared__ float wsum[8];
    if (lane == 0) wsum[warp] = s;
    __syncthreads();
    if (t == 0) {
        float tot = 0.f;
#pragma unroll
        for (int w2 = 0; w2 < 8; w2++) tot += wsum[w2];
        g_tw[r] = g_e1[r] * tot;
    }
}

// ---------------- kernel 4: denom + w_node ordered scan (smem e2) + scale S ----------------
__global__ __launch_bounds__(1024) void wnode_kernel() {
    __shared__ float se2[4096];
    __shared__ int warp_sums[32];
    __shared__ float redf[32];
    __shared__ int s_base;
    __shared__ float s_inv;
    const int t = threadIdx.x, lane = t & 31, warp = t >> 5;

    // cache e2 in smem; reduce denom = sum_r g_tw[r]
    float sd = 0.f;
#pragma unroll
    for (int i = 0; i < 4; i++) {
        se2[t + i * 1024] = g_e2[t + i * 1024];
        sd += g_tw[t + i * 1024];
    }
#pragma unroll
    for (int d = 16; d; d >>= 1) sd += __shfl_down_sync(0xffffffffu, sd, d);
    if (lane == 0) redf[warp] = sd;
    __syncthreads();
    if (warp == 0) {
        float v = redf[lane];
#pragma unroll
        for (int d = 16; d; d >>= 1) v += __shfl_down_sync(0xffffffffu, v, d);
        if (lane == 0) {
            s_inv = 1.f / v;
            s_base = 0;
        }
    }
    __syncthreads();
    const float inv = s_inv;
    float lmax = 0.f;

    for (int r = 0; r < NN; ++r) {
        int base = s_base;
        if (base >= NN) break;
        // adjh row: 4 halves per thread; nonzero bit-pattern test (1.0h = 0x3C00)
        uint2 av = *(const uint2*)(g_adjh + (size_t)r * 4096 + t * 4);
        int f0 = (av.x & 0xFFFFu) != 0, f1 = (av.x >> 16) != 0;
        int f2 = (av.y & 0xFFFFu) != 0, f3 = (av.y >> 16) != 0;
        int cnt = f0 + f1 + f2 + f3;
        int incl = cnt;
#pragma unroll
        for (int d = 1; d < 32; d <<= 1) {
            int v = __shfl_up_sync(0xffffffffu, incl, d);
            if (lane >= d) incl += v;
        }
        if (lane == 31) warp_sums[warp] = incl;
        __syncthreads();
        if (warp == 0) {
            int v = warp_sums[lane];
#pragma unroll
            for (int d = 1; d < 32; d <<= 1) {
                int u = __shfl_up_sync(0xffffffffu, v, d);
                if (lane >= d) v += u;
            }
            warp_sums[lane] = v;  // inclusive over warps
        }
        __syncthreads();
        int wbase = (warp == 0) ? 0 : warp_sums[warp - 1];
        int o = base + wbase + (incl - cnt);
        float e1r = g_e1[r];
        if (f0) { if (o < NN) { float v = e1r * se2[t * 4 + 0] * inv; g_wnode[o] = v; lmax = fmaxf(lmax, v); } o++; }
        if (f1) { if (o < NN) { float v = e1r * se2[t * 4 + 1] * inv; g_wnode[o] = v; lmax = fmaxf(lmax, v); } o++; }
        if (f2) { if (o < NN) { float v = e1r * se2[t * 4 + 2] * inv; g_wnode[o] = v; lmax = fmaxf(lmax, v); } o++; }
        if (f3) { if (o < NN) { float v = e1r * se2[t * 4 + 3] * inv; g_wnode[o] = v; lmax = fmaxf(lmax, v); } o++; }
        __syncthreads();
        if (t == 0) s_base = base + warp_sums[31];
        __syncthreads();
    }

    // reduce lmax, compute S
#pragma unroll
    for (int d = 16; d; d >>= 1) lmax = fmaxf(lmax, __shfl_down_sync(0xffffffffu, lmax, d));
    if (lane == 0) redf[warp] = lmax;
    __syncthreads();
    if (warp == 0) {
        float v = redf[lane];
#pragma unroll
        for (int d = 16; d; d >>= 1) v = fmaxf(v, __shfl_down_sync(0xffffffffu, v, d));
        if (lane == 0) {
            float hmax = __uint_as_float(g_hmax_bits);
            float denom2 = v * hmax;
            g_S = 4096.f / denom2;
            g_invS = denom2 * (1.f / 4096.f);
        }
    }
}

// ---------------- kernel 5: g = S * wnode .* h -> fp16 [4096][256] ----------------
__global__ __launch_bounds__(128) void gscale_kernel() {
    const int j = blockIdx.x, t = threadIdx.x;
    const float ws = g_wnode[j] * g_S;
    float2 hv = *(const float2*)(g_h + (size_t)j * 256 + t * 2);
    __half2 o;
    o.x = __float2half(ws * hv.x);
    o.y = __float2half(ws * hv.y);
    ((__half2*)g_gh)[j * 128 + t] = o;
}

// ---------------- mma / ldmatrix / cp.async helpers ----------------
__device__ __forceinline__ void mma_f16(float& c0, float& c1, float& c2, float& c3,
                                        uint32_t a0, uint32_t a1, uint32_t a2, uint32_t a3,
                                        uint32_t b0, uint32_t b1) {
    asm volatile(
        "mma.sync.aligned.m16n8k16.row.col.f32.f16.f16.f32 "
        "{%0,%1,%2,%3}, {%4,%5,%6,%7}, {%8,%9}, {%0,%1,%2,%3};\n"
        : "+f"(c0), "+f"(c1), "+f"(c2), "+f"(c3)
        : "r"(a0), "r"(a1), "r"(a2), "r"(a3), "r"(b0), "r"(b1));
}
__device__ __forceinline__ void ldsm4(uint32_t& r0, uint32_t& r1, uint32_t& r2, uint32_t& r3,
                                      uint32_t addr) {
    asm volatile("ldmatrix.sync.aligned.m8n8.x4.shared.b16 {%0,%1,%2,%3}, [%4];"
                 : "=r"(r0), "=r"(r1), "=r"(r2), "=r"(r3)
                 : "r"(addr));
}
__device__ __forceinline__ void ldsm4t(uint32_t& r0, uint32_t& r1, uint32_t& r2, uint32_t& r3,
                                       uint32_t addr) {
    asm volatile("ldmatrix.sync.aligned.m8n8.x4.trans.shared.b16 {%0,%1,%2,%3}, [%4];"
                 : "=r"(r0), "=r"(r1), "=r"(r2), "=r"(r3)
                 : "r"(addr));
}
__device__ __forceinline__ void cp16(uint32_t dst, const void* src) {
    asm volatile("cp.async.cg.shared.global [%0], [%1], 16;" :: "r"(dst), "l"(src));
}
#define CP_COMMIT() asm volatile("cp.async.commit_group;" ::: "memory")
#define CP_WAIT2() asm volatile("cp.async.wait_group 2;" ::: "memory")

// ---------------- kernel 6: HMMA GEMM: part[split] = adjh[mtile] @ g ----------------
// BM=128, BN=256(full), BK=64, splitK=4, 512 threads (16 warps: 4M x 4N),
// 3-stage cp.async pipeline, exactly ONE commit_group per k-iteration.
#define A_STRIDE 72    // halves per A smem row (128 rows)
#define B_STRIDE 264   // halves per B smem row (64 rows)
#define STAGE_HALVES (128 * A_STRIDE + 64 * B_STRIDE)   // 9216 + 16896 = 26112
#define SMEM_DYN (3 * STAGE_HALVES * 2 + 32)

__global__ __launch_bounds__(512, 1) void gemm_out_hmma_kernel() {
    extern __shared__ __align__(16) __half smem[];
    const int t = threadIdx.x;
    const int warp = t >> 5, lane = t & 31;
    const int wm = warp & 3, wn = warp >> 2;
    const int m0 = blockIdx.x * 128;
    const int kbase = blockIdx.y * 1024;

    __half* As[3];
    __half* Bs[3];
#pragma unroll
    for (int s = 0; s < 3; s++) {
        As[s] = smem + s * STAGE_HALVES;
        Bs[s] = As[s] + 128 * A_STRIDE;
    }

    float c[2][8][4];
#pragma unroll
    for (int i = 0; i < 2; i++)
#pragma unroll
        for (int j = 0; j < 8; j++)
#pragma unroll
            for (int q = 0; q < 4; q++) c[i][j][q] = 0.f;

    // ---- stage loader: A 128x64 (1024 chunks), B 64x256 (2048 chunks), 6/thread ----
    auto load_stage = [&](int slot, int kt) {
        const int k0 = kbase + kt * 64;
        uint32_t abase = (uint32_t)__cvta_generic_to_shared(As[slot]);
        uint32_t bbase = (uint32_t)__cvta_generic_to_shared(Bs[slot]);
#pragma unroll
        for (int i = 0; i < 2; i++) {  // A: 1024 chunks
            int q = t + i * 512;
            int row = q >> 3, seg = q & 7;
            cp16(abase + (row * A_STRIDE + seg * 8) * 2,
                 g_adjh + (size_t)(m0 + row) * 4096 + k0 + seg * 8);
        }
#pragma unroll
        for (int i = 0; i < 4; i++) {  // B: 2048 chunks
            int q = t + i * 512;
            int row = q >> 5, seg = q & 31;
            cp16(bbase + (row * B_STRIDE + seg * 8) * 2,
                 g_gh + (size_t)(k0 + row) * 256 + seg * 8);
        }
        CP_COMMIT();
    };

    load_stage(0, 0);
    load_stage(1, 1);
    load_stage(2, 2);

    for (int kt = 0; kt < 16; ++kt) {
        const int slot = kt % 3;
        CP_WAIT2();
        __syncthreads();
        const __half* a_s = As[slot];
        const __half* b_s = Bs[slot];
#pragma unroll
        for (int ks = 0; ks < 4; ++ks) {
            uint32_t a[2][4];
#pragma unroll
            for (int mi = 0; mi < 2; ++mi) {
                int row = wm * 32 + mi * 16 + (lane & 15);
                int col = ks * 16 + ((lane >> 4) << 3);
                uint32_t addr =
                    (uint32_t)__cvta_generic_to_shared(a_s + row * A_STRIDE + col);
                ldsm4(a[mi][0], a[mi][1], a[mi][2], a[mi][3], addr);
            }
#pragma unroll
            for (int ng = 0; ng < 4; ++ng) {
                int krow = ks * 16 + (lane & 15);
                int col = wn * 64 + ng * 16 + ((lane >> 4) << 3);
                uint32_t b0, b1, b2, b3;
                uint32_t addr =
                    (uint32_t)__cvta_generic_to_shared(b_s + krow * B_STRIDE + col);
                ldsm4t(b0, b1, b2, b3, addr);
#pragma unroll
                for (int mi = 0; mi < 2; ++mi) {
                    mma_f16(c[mi][ng * 2][0], c[mi][ng * 2][1],
                            c[mi][ng * 2][2], c[mi][ng * 2][3],
                            a[mi][0], a[mi][1], a[mi][2], a[mi][3], b0, b1);
                    mma_f16(c[mi][ng * 2 + 1][0], c[mi][ng * 2 + 1][1],
                            c[mi][ng * 2 + 1][2], c[mi][ng * 2 + 1][3],
                            a[mi][0], a[mi][1], a[mi][2], a[mi][3], b2, b3);
                }
            }
        }
        __syncthreads();
        if (kt + 3 < 16) load_stage(slot, kt + 3);
        else CP_COMMIT();  // keep exactly one group per iteration
    }

    // epilogue: fp32 partials
    float* dst = g_part + (size_t)blockIdx.y * NN * FF;
    const int g = lane >> 2, tg = lane & 3;
#pragma unroll
    for (int mi = 0; mi < 2; ++mi) {
        int row0 = m0 + wm * 32 + mi * 16 + g;
#pragma unroll
        for (int nb = 0; nb < 8; ++nb) {
            int col = wn * 64 + nb * 8 + tg * 2;
            float2 v0 = {c[mi][nb][0], c[mi][nb][1]};
            float2 v1 = {c[mi][nb][2], c[mi][nb][3]};
            *(float2*)(dst + (size_t)row0 * 256 + col) = v0;
            *(float2*)(dst + (size_t)(row0 + 8) * 256 + col) = v1;
        }
    }
}

// ---------------- kernel 7: out = relu(sum partials) * invS ----------------
__global__ __launch_bounds__(256) void relu_sum_kernel(float* __restrict__ out) {
    const float invS = g_invS;
    const size_t idx = (size_t)(blockIdx.x * 256 + threadIdx.x) * 4;
    float4 a = *(const float4*)(g_part + idx);
    float4 b = *(const float4*)(g_part + (size_t)NN * FF + idx);
    float4 c = *(const float4*)(g_part + 2 * (size_t)NN * FF + idx);
    float4 d = *(const float4*)(g_part + 3 * (size_t)NN * FF + idx);
    float4 v;
    v.x = fmaxf(a.x + b.x + c.x + d.x, 0.f) * invS;
    v.y = fmaxf(a.y + b.y + c.y + d.y, 0.f) * invS;
    v.z = fmaxf(a.z + b.z + c.z + d.z, 0.f) * invS;
    v.w = fmaxf(a.w + b.w + c.w + d.w, 0.f) * invS;
    *(float4*)(out + idx) = v;
}

// ---------------- launch ----------------
extern "C" void kernel_launch(void* const* d_in, const int* in_sizes, int n_in,
                              void* d_out, int out_size) {
    const float* x = (const float*)d_in[0];
    const int* adj = (const int*)d_in[1];
    const float* W = (const float*)d_in[2];
    const float* b = (const float*)d_in[3];
    const float* att_w = (const float*)d_in[4];
    // att_b cancels in the softmax ratio; unused.
    float* out = (float*)d_out;

    static bool attr_set = false;
    if (!attr_set) {
        cudaFuncSetAttribute(gemm_out_hmma_kernel,
                             cudaFuncAttributeMaxDynamicSharedMemorySize, SMEM_DYN);
        attr_set = true;
    }

    gemm_h_kernel<<<dim3(64, 4), 256>>>(x, W, b);
    a12_kernel<<<512, 256>>>(att_w);
    row_stats_kernel<<<4096, 256>>>(adj);
    wnode_kernel<<<1, 1024>>>();
    gscale_kernel<<<4096, 128>>>();
    gemm_out_hmma_kernel<<<dim3(32, 4), 512, SMEM_DYN>>>();
    relu_sum_kernel<<<1024, 256>>>(out);
}

// round 7
// speedup vs baseline: 1.4560x; 1.4560x over previous
#include <cuda_runtime.h>
#include <cuda_fp16.h>
#include <cstdint>

#define NN 4096
#define FF 256

// ---------------- scratch (device globals; no allocations) ----------------
__device__ float g_h[NN * FF];                    // 4 MB fp32 h
__device__ float g_e1[NN];
__device__ float g_e2[NN];
__device__ float g_tw[NN];                        // e1[r] * t[r]
__device__ float g_wnode[NN];
__device__ int g_cnt[NN];                         // edges per row
__device__ int g_rowbase[NN];                     // exclusive prefix of g_cnt
__device__ float g_inv;                           // 1 / denom
__device__ unsigned int g_hmax_bits;              // max |h| (float bits, >=0)
__device__ unsigned int g_wmax_bits;              // max wnode (float bits, >=0)
__device__ __half g_adjh[(size_t)NN * NN];        // 32 MB  adj as fp16 [4096][4096]
__device__ __half g_gh[(size_t)NN * FF];          // 2 MB   S * wnode_j * h[j][n], fp16
__device__ float g_part[4 * (size_t)NN * FF];     // 16 MB  split-K partials

// ---------------- kernel 1: h = x @ W^T + b (fp32 SIMT tiled) ----------------
__global__ __launch_bounds__(256) void gemm_h_kernel(const float* __restrict__ x,
                                                     const float* __restrict__ W,
                                                     const float* __restrict__ b) {
    __shared__ __align__(16) float xs[16][68];
    __shared__ __align__(16) float ws[16][68];
    const int t = threadIdx.x;
    const int tx = t & 15, ty = t >> 4;
    const int bm = blockIdx.x, bn = blockIdx.y;
    const int r = t >> 2, seg = t & 3;

    float acc[4][4];
#pragma unroll
    for (int i = 0; i < 4; i++)
#pragma unroll
        for (int j = 0; j < 4; j++) acc[i][j] = 0.f;

    for (int kt = 0; kt < 16; ++kt) {
        float4 xv = *(const float4*)(x + (size_t)(bm * 64 + r) * 256 + kt * 16 + seg * 4);
        float4 wv = *(const float4*)(W + (size_t)(bn * 64 + r) * 256 + kt * 16 + seg * 4);
        xs[seg * 4 + 0][r] = xv.x; xs[seg * 4 + 1][r] = xv.y;
        xs[seg * 4 + 2][r] = xv.z; xs[seg * 4 + 3][r] = xv.w;
        ws[seg * 4 + 0][r] = wv.x; ws[seg * 4 + 1][r] = wv.y;
        ws[seg * 4 + 2][r] = wv.z; ws[seg * 4 + 3][r] = wv.w;
        __syncthreads();
#pragma unroll
        for (int k = 0; k < 16; ++k) {
            float4 xa = *(const float4*)&xs[k][ty * 4];
            float4 wb = *(const float4*)&ws[k][tx * 4];
            float xr[4] = {xa.x, xa.y, xa.z, xa.w};
            float wr[4] = {wb.x, wb.y, wb.z, wb.w};
#pragma unroll
            for (int i = 0; i < 4; i++)
#pragma unroll
                for (int j = 0; j < 4; j++) acc[i][j] += xr[i] * wr[j];
        }
        __syncthreads();
    }
#pragma unroll
    for (int i = 0; i < 4; i++) {
        int row = bm * 64 + ty * 4 + i;
#pragma unroll
        for (int j = 0; j < 4; j++) {
            int col = bn * 64 + tx * 4 + j;
            g_h[(size_t)row * 256 + col] = acc[i][j] + b[col];
        }
    }
}

// ---------------- kernel 2: e1/e2 = exp(h.w1/2); also global max|h| ----------------
__global__ __launch_bounds__(256) void a12_kernel(const float* __restrict__ att_w) {
    __shared__ float aw[512];
    const int t = threadIdx.x;
    aw[t] = att_w[t];
    aw[t + 256] = att_w[t + 256];
    __syncthreads();
    const int warp = t >> 5, lane = t & 31;
    const int row = blockIdx.x * 8 + warp;
    const float* hr = g_h + (size_t)row * 256;
    float s1 = 0.f, s2 = 0.f, hm = 0.f;
#pragma unroll
    for (int q = 0; q < 2; q++) {
        int f = lane * 8 + q * 4;
        float4 hv = *(const float4*)(hr + f);
        float4 w1 = *(const float4*)(aw + f);
        float4 w2 = *(const float4*)(aw + 256 + f);
        s1 += hv.x * w1.x + hv.y * w1.y + hv.z * w1.z + hv.w * w1.w;
        s2 += hv.x * w2.x + hv.y * w2.y + hv.z * w2.z + hv.w * w2.w;
        hm = fmaxf(hm, fmaxf(fmaxf(fabsf(hv.x), fabsf(hv.y)),
                             fmaxf(fabsf(hv.z), fabsf(hv.w))));
    }
#pragma unroll
    for (int d = 16; d; d >>= 1) {
        s1 += __shfl_down_sync(0xffffffffu, s1, d);
        s2 += __shfl_down_sync(0xffffffffu, s2, d);
        hm = fmaxf(hm, __shfl_down_sync(0xffffffffu, hm, d));
    }
    if (lane == 0) {
        g_e1[row] = expf(s1);
        g_e2[row] = expf(s2);
        atomicMax(&g_hmax_bits, __float_as_uint(hm));  // |h|>=0: uint order == float order
    }
}

// ---------------- kernel 3: t, adj->fp16, edge counts, tw = e1*t ----------------
__global__ __launch_bounds__(256) void row_stats_kernel(const int* __restrict__ adj) {
    const int r = blockIdx.x, t = threadIdx.x;
    const int4* arow = (const int4*)(adj + (size_t)r * 4096) + t * 4;
    float s = 0.f;
    int ic = 0;
    __align__(16) __half ob[16];
#pragma unroll
    for (int q = 0; q < 4; q++) {
        int4 a = arow[q];
        int j = t * 16 + q * 4;
        float4 ev = *(const float4*)(g_e2 + j);
        int f0 = (a.x == 1), f1 = (a.y == 1), f2 = (a.z == 1), f3 = (a.w == 1);
        s += (f0 ? ev.x : 0.f) + (f1 ? ev.y : 0.f) + (f2 ? ev.z : 0.f) + (f3 ? ev.w : 0.f);
        ic += f0 + f1 + f2 + f3;
        ob[q * 4 + 0] = __ushort_as_half(f0 ? (unsigned short)0x3C00 : (unsigned short)0);
        ob[q * 4 + 1] = __ushort_as_half(f1 ? (unsigned short)0x3C00 : (unsigned short)0);
        ob[q * 4 + 2] = __ushort_as_half(f2 ? (unsigned short)0x3C00 : (unsigned short)0);
        ob[q * 4 + 3] = __ushort_as_half(f3 ? (unsigned short)0x3C00 : (unsigned short)0);
    }
    int4* dst = (int4*)(g_adjh + (size_t)r * 4096 + t * 16);
    dst[0] = ((int4*)ob)[0];
    dst[1] = ((int4*)ob)[1];
    const int lane = t & 31, warp = t >> 5;
#pragma unroll
    for (int d = 16; d; d >>= 1) {
        s += __shfl_down_sync(0xffffffffu, s, d);
        ic += __shfl_down_sync(0xffffffffu, ic, d);
    }
    __shared__ float wsum[8];
    __shared__ int wcnt[8];
    if (lane == 0) { wsum[warp] = s; wcnt[warp] = ic; }
    __syncthreads();
    if (t == 0) {
        float tot = 0.f;
        int ct = 0;
#pragma unroll
        for (int w2 = 0; w2 < 8; w2++) { tot += wsum[w2]; ct += wcnt[w2]; }
        g_tw[r] = g_e1[r] * tot;
        g_cnt[r] = ct;
    }
}

// ---------------- kernel 4: prefix of counts -> rowbase; denom -> g_inv ----------------
__global__ __launch_bounds__(1024) void scan_kernel() {
    __shared__ int wscan[32];
    __shared__ float redf[32];
    const int t = threadIdx.x, lane = t & 31, warp = t >> 5;

    int4 c = *(const int4*)(g_cnt + t * 4);
    int s0 = c.x, s1 = s0 + c.y, s2 = s1 + c.z, s3 = s2 + c.w;
    int incl = s3;
#pragma unroll
    for (int d = 1; d < 32; d <<= 1) {
        int v = __shfl_up_sync(0xffffffffu, incl, d);
        if (lane >= d) incl += v;
    }
    if (lane == 31) wscan[warp] = incl;

    // denom reduce (overlap with scan)
    float sd = 0.f;
#pragma unroll
    for (int i = 0; i < 4; i++) sd += g_tw[t + i * 1024];
#pragma unroll
    for (int d = 16; d; d >>= 1) sd += __shfl_down_sync(0xffffffffu, sd, d);
    if (lane == 0) redf[warp] = sd;
    __syncthreads();
    if (warp == 0) {
        int v = wscan[lane];
#pragma unroll
        for (int d = 1; d < 32; d <<= 1) {
            int u = __shfl_up_sync(0xffffffffu, v, d);
            if (lane >= d) v += u;
        }
        wscan[lane] = v;  // inclusive
        float f = redf[lane];
#pragma unroll
        for (int d = 16; d; d >>= 1) f += __shfl_down_sync(0xffffffffu, f, d);
        if (lane == 0) g_inv = 1.f / f;
    }
    __syncthreads();
    int base = ((warp == 0) ? 0 : wscan[warp - 1]) + incl - s3;  // exclusive
    int4 rb;
    rb.x = base;
    rb.y = base + s0;
    rb.z = base + s1;
    rb.w = base + s2;
    *(int4*)(g_rowbase + t * 4) = rb;
}

// ---------------- kernel 5: emit w_node ranks (parallel over rows) ----------------
__global__ __launch_bounds__(256) void emit_kernel() {
    const int t = threadIdx.x, lane = t & 31, warp = t >> 5;
    __shared__ int wpre[8];
    float lmax = 0.f;
    const float inv = g_inv;

    for (int r = blockIdx.x; r < NN; r += gridDim.x) {
        int base = g_rowbase[r];
        if (base >= NN) break;  // rowbase monotone: later rows also out
        // 16 halves per thread from adjh row
        uint4 a0 = *(const uint4*)(g_adjh + (size_t)r * 4096 + t * 16);
        uint4 a1 = *(const uint4*)(g_adjh + (size_t)r * 4096 + t * 16 + 8);
        uint32_t wd[8] = {a0.x, a0.y, a0.z, a0.w, a1.x, a1.y, a1.z, a1.w};
        int flags[16];
        int cnt = 0;
#pragma unroll
        for (int q = 0; q < 8; q++) {
            flags[q * 2] = (wd[q] & 0xFFFFu) != 0;
            flags[q * 2 + 1] = (wd[q] >> 16) != 0;
            cnt += flags[q * 2] + flags[q * 2 + 1];
        }
        int incl = cnt;
#pragma unroll
        for (int d = 1; d < 32; d <<= 1) {
            int v = __shfl_up_sync(0xffffffffu, incl, d);
            if (lane >= d) incl += v;
        }
        if (lane == 31) wpre[warp] = incl;
        __syncthreads();
        int wbase = 0;
#pragma unroll
        for (int u = 0; u < 8; u++) wbase += (u < warp) ? wpre[u] : 0;
        int pos = base + wbase + incl - cnt;
        float e1r = g_e1[r];
#pragma unroll
        for (int q = 0; q < 16; q++) {
            if (flags[q]) {
                if (pos < NN) {
                    float v = e1r * g_e2[t * 16 + q] * inv;
                    g_wnode[pos] = v;
                    lmax = fmaxf(lmax, v);
                }
                pos++;
            }
        }
        __syncthreads();
    }
#pragma unroll
    for (int d = 16; d; d >>= 1) lmax = fmaxf(lmax, __shfl_down_sync(0xffffffffu, lmax, d));
    if (lane == 0 && lmax > 0.f) atomicMax(&g_wmax_bits, __float_as_uint(lmax));
}

// ---------------- kernel 6: g = S * wnode .* h -> fp16 (S inline) ----------------
__global__ __launch_bounds__(128) void gscale_kernel() {
    const int j = blockIdx.x, t = threadIdx.x;
    const float S = 4096.f / (__uint_as_float(g_wmax_bits) * __uint_as_float(g_hmax_bits));
    const float ws = g_wnode[j] * S;
    float2 hv = *(const float2*)(g_h + (size_t)j * 256 + t * 2);
    __half2 o;
    o.x = __float2half(ws * hv.x);
    o.y = __float2half(ws * hv.y);
    ((__half2*)g_gh)[j * 128 + t] = o;
}

// ---------------- mma / ldmatrix / cp.async helpers ----------------
__device__ __forceinline__ void mma_f16(float& c0, float& c1, float& c2, float& c3,
                                        uint32_t a0, uint32_t a1, uint32_t a2, uint32_t a3,
                                        uint32_t b0, uint32_t b1) {
    asm volatile(
        "mma.sync.aligned.m16n8k16.row.col.f32.f16.f16.f32 "
        "{%0,%1,%2,%3}, {%4,%5,%6,%7}, {%8,%9}, {%0,%1,%2,%3};\n"
        : "+f"(c0), "+f"(c1), "+f"(c2), "+f"(c3)
        : "r"(a0), "r"(a1), "r"(a2), "r"(a3), "r"(b0), "r"(b1));
}
__device__ __forceinline__ void ldsm4(uint32_t& r0, uint32_t& r1, uint32_t& r2, uint32_t& r3,
                                      uint32_t addr) {
    asm volatile("ldmatrix.sync.aligned.m8n8.x4.shared.b16 {%0,%1,%2,%3}, [%4];"
                 : "=r"(r0), "=r"(r1), "=r"(r2), "=r"(r3)
                 : "r"(addr));
}
__device__ __forceinline__ void ldsm4t(uint32_t& r0, uint32_t& r1, uint32_t& r2, uint32_t& r3,
                                       uint32_t addr) {
    asm volatile("ldmatrix.sync.aligned.m8n8.x4.trans.shared.b16 {%0,%1,%2,%3}, [%4];"
                 : "=r"(r0), "=r"(r1), "=r"(r2), "=r"(r3)
                 : "r"(addr));
}
__device__ __forceinline__ void cp16(uint32_t dst, const void* src) {
    asm volatile("cp.async.cg.shared.global [%0], [%1], 16;" :: "r"(dst), "l"(src));
}
#define CP_COMMIT() asm volatile("cp.async.commit_group;" ::: "memory")
#define CP_WAIT2() asm volatile("cp.async.wait_group 2;" ::: "memory")

// ---------------- kernel 7: HMMA GEMM (EXACT R3 structure) ----------------
// BM=128, BN=256(full), BK=64, splitK=4, 512 threads (16 warps: 4M x 4N),
// 3-stage cp.async, R3's double-commit pattern (empirically fastest).
#define A_STRIDE 72    // halves per A smem row (128 rows)
#define B_STRIDE 264   // halves per B smem row (64 rows)
#define STAGE_HALVES (128 * A_STRIDE + 64 * B_STRIDE)   // 9216 + 16896 = 26112
#define SMEM_DYN (3 * STAGE_HALVES * 2 + 32)

__global__ __launch_bounds__(512, 1) void gemm_out_hmma_kernel() {
    extern __shared__ __align__(16) __half smem[];
    const int t = threadIdx.x;
    const int warp = t >> 5, lane = t & 31;
    const int wm = warp & 3, wn = warp >> 2;
    const int m0 = blockIdx.x * 128;
    const int kbase = blockIdx.y * 1024;

    __half* As[3];
    __half* Bs[3];
#pragma unroll
    for (int s = 0; s < 3; s++) {
        As[s] = smem + s * STAGE_HALVES;
        Bs[s] = As[s] + 128 * A_STRIDE;
    }

    float c[2][8][4];
#pragma unroll
    for (int i = 0; i < 2; i++)
#pragma unroll
        for (int j = 0; j < 8; j++)
#pragma unroll
            for (int q = 0; q < 4; q++) c[i][j][q] = 0.f;

    auto load_stage = [&](int slot, int kt) {
        const int k0 = kbase + kt * 64;
        uint32_t abase = (uint32_t)__cvta_generic_to_shared(As[slot]);
        uint32_t bbase = (uint32_t)__cvta_generic_to_shared(Bs[slot]);
#pragma unroll
        for (int i = 0; i < 2; i++) {  // A: 1024 chunks
            int q = t + i * 512;
            int row = q >> 3, seg = q & 7;
            cp16(abase + (row * A_STRIDE + seg * 8) * 2,
                 g_adjh + (size_t)(m0 + row) * 4096 + k0 + seg * 8);
        }
#pragma unroll
        for (int i = 0; i < 4; i++) {  // B: 2048 chunks
            int q = t + i * 512;
            int row = q >> 5, seg = q & 31;
            cp16(bbase + (row * B_STRIDE + seg * 8) * 2,
                 g_gh + (size_t)(k0 + row) * 256 + seg * 8);
        }
        CP_COMMIT();
    };

    load_stage(0, 0);
    load_stage(1, 1);
    load_stage(2, 2);

    for (int kt = 0; kt < 16; ++kt) {
        const int slot = kt % 3;
        CP_WAIT2();
        __syncthreads();
        const __half* a_s = As[slot];
        const __half* b_s = Bs[slot];
#pragma unroll
        for (int ks = 0; ks < 4; ++ks) {
            uint32_t a[2][4];
#pragma unroll
            for (int mi = 0; mi < 2; ++mi) {
                int row = wm * 32 + mi * 16 + (lane & 15);
                int col = ks * 16 + ((lane >> 4) << 3);
                uint32_t addr =
                    (uint32_t)__cvta_generic_to_shared(a_s + row * A_STRIDE + col);
                ldsm4(a[mi][0], a[mi][1], a[mi][2], a[mi][3], addr);
            }
#pragma unroll
            for (int ng = 0; ng < 4; ++ng) {
                int krow = ks * 16 + (lane & 15);
                int col = wn * 64 + ng * 16 + ((lane >> 4) << 3);
                uint32_t b0, b1, b2, b3;
                uint32_t addr =
                    (uint32_t)__cvta_generic_to_shared(b_s + krow * B_STRIDE + col);
                ldsm4t(b0, b1, b2, b3, addr);
#pragma unroll
                for (int mi = 0; mi < 2; ++mi) {
                    mma_f16(c[mi][ng * 2][0], c[mi][ng * 2][1],
                            c[mi][ng * 2][2], c[mi][ng * 2][3],
                            a[mi][0], a[mi][1], a[mi][2], a[mi][3], b0, b1);
                    mma_f16(c[mi][ng * 2 + 1][0], c[mi][ng * 2 + 1][1],
                            c[mi][ng * 2 + 1][2], c[mi][ng * 2 + 1][3],
                            a[mi][0], a[mi][1], a[mi][2], a[mi][3], b2, b3);
                }
            }
        }
        __syncthreads();
        if (kt + 3 < 16) load_stage(slot, kt + 3);
        CP_COMMIT();  // R3 pattern: unconditional extra group each iteration
    }

    // epilogue: fp32 partials
    float* dst = g_part + (size_t)blockIdx.y * NN * FF;
    const int g = lane >> 2, tg = lane & 3;
#pragma unroll
    for (int mi = 0; mi < 2; ++mi) {
        int row0 = m0 + wm * 32 + mi * 16 + g;
#pragma unroll
        for (int nb = 0; nb < 8; ++nb) {
            int col = wn * 64 + nb * 8 + tg * 2;
            float2 v0 = {c[mi][nb][0], c[mi][nb][1]};
            float2 v1 = {c[mi][nb][2], c[mi][nb][3]};
            *(float2*)(dst + (size_t)row0 * 256 + col) = v0;
            *(float2*)(dst + (size_t)(row0 + 8) * 256 + col) = v1;
        }
    }
}

// ---------------- kernel 8: out = relu(sum partials) * invS ----------------
__global__ __launch_bounds__(256) void relu_sum_kernel(float* __restrict__ out) {
    const float invS =
        (__uint_as_float(g_wmax_bits) * __uint_as_float(g_hmax_bits)) * (1.f / 4096.f);
    const size_t idx = (size_t)(blockIdx.x * 256 + threadIdx.x) * 4;
    float4 a = *(const float4*)(g_part + idx);
    float4 b = *(const float4*)(g_part + (size_t)NN * FF + idx);
    float4 c = *(const float4*)(g_part + 2 * (size_t)NN * FF + idx);
    float4 d = *(const float4*)(g_part + 3 * (size_t)NN * FF + idx);
    float4 v;
    v.x = fmaxf(a.x + b.x + c.x + d.x, 0.f) * invS;
    v.y = fmaxf(a.y + b.y + c.y + d.y, 0.f) * invS;
    v.z = fmaxf(a.z + b.z + c.z + d.z, 0.f) * invS;
    v.w = fmaxf(a.w + b.w + c.w + d.w, 0.f) * invS;
    *(float4*)(out + idx) = v;
}

// ---------------- launch ----------------
extern "C" void kernel_launch(void* const* d_in, const int* in_sizes, int n_in,
                              void* d_out, int out_size) {
    const float* x = (const float*)d_in[0];
    const int* adj = (const int*)d_in[1];
    const float* W = (const float*)d_in[2];
    const float* b = (const float*)d_in[3];
    const float* att_w = (const float*)d_in[4];
    // att_b cancels in the softmax ratio; unused.
    float* out = (float*)d_out;

    static bool attr_set = false;
    if (!attr_set) {
        cudaFuncSetAttribute(gemm_out_hmma_kernel,
                             cudaFuncAttributeMaxDynamicSharedMemorySize, SMEM_DYN);
        attr_set = true;
    }

    gemm_h_kernel<<<dim3(64, 4), 256>>>(x, W, b);
    a12_kernel<<<512, 256>>>(att_w);
    row_stats_kernel<<<4096, 256>>>(adj);
    scan_kernel<<<1, 1024>>>();
    emit_kernel<<<64, 256>>>();
    gscale_kernel<<<4096, 128>>>();
    gemm_out_hmma_kernel<<<dim3(32, 4), 512, SMEM_DYN>>>();
    relu_sum_kernel<<<1024, 256>>>(out);
}